// round 8
// baseline (speedup 1.0000x reference)
#include <cuda_runtime.h>
#include <cuda_fp16.h>
#include <cstdint>
#include <cstddef>

// Problem constants
#define Bsz  32
#define Rn   16384
#define Cn   16
#define Od   16

#define WARPS 8
#define PAIRS 4                   // warp pairs per block (route)
#define RPW   64                  // r per warp-pair in route
#define RBLK  (PAIRS * RPW)       // 256 r per block
#define PRPW  32                  // r per warp in prep
#define PRBLK (WARPS * PRPW)      // 256 r per prep block

// ---------------- scratch (device globals; no allocation allowed) ----------
__device__ uint4 g_Wh4[(size_t)Rn * Cn * 32 + 32];  // 134 MB fp16 W, frag-packed
__device__ float g_Wsum[Cn * 256];              // sum over r of W  [c][o][i]
__device__ float g_v0[Bsz * Cn * Od];
__device__ float g_vsum[Bsz * Cn * Od];         // v0 + v1
__device__ float g_sraw[Bsz * Cn * Od];         // un-normalized weighted sums
__device__ float g_sumexp[Bsz * Cn];            // sum of exp(logit) per (b,c)

// ---------------- helpers ---------------------------------------------------
__device__ __forceinline__ uint32_t packh2(float a, float b) {
    __half2 h = __floats2half2_rn(a, b);
    return *reinterpret_cast<uint32_t*>(&h);
}

union F2U { float2 f; unsigned long long u; };

__device__ __forceinline__ float2 ffma2(float2 a, float2 b, float2 c) {
    F2U A, B, C, D; A.f = a; B.f = b; C.f = c;
    asm("fma.rn.f32x2 %0, %1, %2, %3;" : "=l"(D.u) : "l"(A.u), "l"(B.u), "l"(C.u));
    return D.f;
}
__device__ __forceinline__ float2 fmul2(float2 a, float2 b) {
    F2U A, B, D; A.f = a; B.f = b;
    asm("mul.rn.f32x2 %0, %1, %2;" : "=l"(D.u) : "l"(A.u), "l"(B.u));
    return D.f;
}

// mma m16n8k16: dA = rows g (b-low), dB = rows g+8 (b-high), cols = 2 o's
__device__ __forceinline__ void mma16816(float2& dA, float2& dB, const uint32_t* a,
                                         uint32_t b0, uint32_t b1) {
    asm volatile(
        "mma.sync.aligned.m16n8k16.row.col.f32.f16.f16.f32 "
        "{%0,%1,%2,%3}, {%4,%5,%6,%7}, {%8,%9}, {%10,%11,%12,%13};\n"
        : "=f"(dA.x), "=f"(dA.y), "=f"(dB.x), "=f"(dB.y)
        : "r"(a[0]), "r"(a[1]), "r"(a[2]), "r"(a[3]),
          "r"(b0), "r"(b1),
          "f"(0.f), "f"(0.f), "f"(0.f), "f"(0.f));
}

// ---------------- K0: zero accumulators (per replay) -----------------------
__global__ void k_zero() {
    int i = blockIdx.x * blockDim.x + threadIdx.x;
    if (i < Cn * 256)       g_Wsum[i] = 0.f;
    if (i < Bsz * Cn * Od)  g_sraw[i] = 0.f;
    if (i < Bsz * Cn)       g_sumexp[i] = 0.f;
}

// ---------------- K1: prep — convert W to packed fp16 frags + Wsum ---------
__global__ __launch_bounds__(256) void k_prep(const float* __restrict__ W) {
    const int c    = blockIdx.y;
    const int tid  = threadIdx.x;
    const int wid  = tid >> 5;
    const int lane = tid & 31;
    const int g    = lane >> 2;
    const int tg   = lane & 3;
    const int r0   = blockIdx.x * PRBLK + wid * PRPW;

    float ws[8];
#pragma unroll
    for (int j = 0; j < 8; j++) ws[j] = 0.f;

#pragma unroll 16
    for (int k = 0; k < PRPW; k++) {
        const float2* row = reinterpret_cast<const float2*>(
            &W[((size_t)(r0 + k) * Cn + c) * 256]);
        float2 f0 = __ldcs(&row[g * 8 + tg]);
        float2 f1 = __ldcs(&row[g * 8 + tg + 4]);
        float2 f2 = __ldcs(&row[(g + 8) * 8 + tg]);
        float2 f3 = __ldcs(&row[(g + 8) * 8 + tg + 4]);
        ws[0] += f0.x; ws[1] += f0.y; ws[2] += f1.x; ws[3] += f1.y;
        ws[4] += f2.x; ws[5] += f2.y; ws[6] += f3.x; ws[7] += f3.y;
        uint4 o;
        o.x = packh2(f0.x, f0.y); o.y = packh2(f1.x, f1.y);
        o.z = packh2(f2.x, f2.y); o.w = packh2(f3.x, f3.y);
        __stcs(&g_Wh4[((size_t)c * Rn + (r0 + k)) * 32 + lane], o);
    }

    // fold Wsum partials: positions per lane are a bijection onto 0..255
    __shared__ float s_ws[WARPS][256];
    const int p0 = g * 16 + 2 * tg;        // (o=g,   i=2tg)
    const int p2 = (g + 8) * 16 + 2 * tg;  // (o=g+8, i=2tg)
    s_ws[wid][p0]     = ws[0]; s_ws[wid][p0 + 1] = ws[1];
    s_ws[wid][p0 + 8] = ws[2]; s_ws[wid][p0 + 9] = ws[3];
    s_ws[wid][p2]     = ws[4]; s_ws[wid][p2 + 1] = ws[5];
    s_ws[wid][p2 + 8] = ws[6]; s_ws[wid][p2 + 9] = ws[7];
    __syncthreads();
    float s = 0.f;
#pragma unroll
    for (int w = 0; w < WARPS; w++) s += s_ws[w][tid];
    atomicAdd(&g_Wsum[c * 256 + tid], s);
}

// ---------------- K2: v0 = squash((1/R) * Wsum . x) ------------------------
__global__ void k_v0(const float* __restrict__ x) {
    int t = blockIdx.x * blockDim.x + threadIdx.x;
    if (t >= Bsz * Cn) return;
    const int b = t >> 4, c = t & 15;
    float s[16], n2 = 0.f;
#pragma unroll
    for (int o = 0; o < 16; o++) {
        float acc = 0.f;
#pragma unroll
        for (int i = 0; i < 16; i++)
            acc = fmaf(g_Wsum[(c * 16 + o) * 16 + i], x[(b * Cn + c) * 16 + i], acc);
        acc *= (1.f / (float)Rn);
        s[o] = acc; n2 += acc * acc;
    }
    const float norm = sqrtf(n2);
    const float sc = norm / (1.f + n2);
#pragma unroll
    for (int o = 0; o < 16; o++) g_v0[t * 16 + o] = sc * s[o];
}

// ---------------- K3: fused routing pass (HMMA, b split across warp pairs) --
// rev=1 reverses the block traversal order so this pass consumes g_Wh4 in the
// opposite order of the previous pass's completion — the overlap with what is
// still resident in L2 (126MB vs 134MB footprint) becomes a hit stream.
__global__ __launch_bounds__(256, 5) void k_route_mma(const float* __restrict__ x,
                                                      const float* __restrict__ vsrc,
                                                      int rev) {
    int bx = blockIdx.x, by = blockIdx.y;
    if (rev) { bx = gridDim.x - 1 - bx; by = gridDim.y - 1 - by; }
    const int c    = by;
    const int tid  = threadIdx.x;
    const int wid  = tid >> 5;
    const int lane = tid & 31;
    const int g    = lane >> 2;
    const int tg   = lane & 3;
    const int pair = wid >> 1;
    const int pb   = wid & 1;     // b-half: 0 -> b 0-15, 1 -> b 16-31

    // ---- A fragments from x (fp32 -> fp16), M = 16 b's of this half ----
    uint32_t A[4];
    {
        const int b_lo = pb * 16 + g, b_hi = pb * 16 + 8 + g;
#pragma unroll
        for (int kh = 0; kh < 2; kh++) {
            float2 lo = *reinterpret_cast<const float2*>(&x[(b_lo * Cn + c) * 16 + 2 * tg + kh * 8]);
            float2 hi = *reinterpret_cast<const float2*>(&x[(b_hi * Cn + c) * 16 + 2 * tg + kh * 8]);
            A[kh * 2 + 0] = packh2(lo.x, lo.y);
            A[kh * 2 + 1] = packh2(hi.x, hi.y);
        }
    }

    // ---- v pairs for this lane's (b,o) positions ----
    float2 vv2[4];
    {
        const int b_lo = pb * 16 + g, b_hi = pb * 16 + 8 + g;
        vv2[0] = *reinterpret_cast<const float2*>(&vsrc[(b_lo * Cn + c) * 16 + 2 * tg]);
        vv2[1] = *reinterpret_cast<const float2*>(&vsrc[(b_lo * Cn + c) * 16 + 2 * tg + 8]);
        vv2[2] = *reinterpret_cast<const float2*>(&vsrc[(b_hi * Cn + c) * 16 + 2 * tg]);
        vv2[3] = *reinterpret_cast<const float2*>(&vsrc[(b_hi * Cn + c) * 16 + 2 * tg + 8]);
    }

    float2 acc2[4];
#pragma unroll
    for (int j = 0; j < 4; j++) acc2[j] = make_float2(0.f, 0.f);
    float esum0 = 0.f, esum1 = 0.f;

    const int r0 = bx * RBLK + pair * RPW;
    const uint4* __restrict__ Wq = g_Wh4 + ((size_t)c * Rn + r0) * 32 + lane;

#pragma unroll 4
    for (int k = 0; k < RPW; k++) {
        const uint4 cur = Wq[k * 32];

        float2 dA1, dB1, dA2, dB2;
        mma16816(dA1, dB1, A, cur.x, cur.y);   // o 0-7   (dA=b_lo, dB=b_hi)
        mma16816(dA2, dB2, A, cur.z, cur.w);   // o 8-15

        // logit partials (each lane: its 4 o's), packed f32x2
        float2 q0 = ffma2(dA2, vv2[1], fmul2(dA1, vv2[0]));
        float2 q1 = ffma2(dB2, vv2[3], fmul2(dB1, vv2[2]));
        float p0 = q0.x + q0.y;
        float p1 = q1.x + q1.y;
        p0 += __shfl_xor_sync(0xffffffffu, p0, 1);
        p0 += __shfl_xor_sync(0xffffffffu, p0, 2);
        p1 += __shfl_xor_sync(0xffffffffu, p1, 1);
        p1 += __shfl_xor_sync(0xffffffffu, p1, 2);

        const float w0 = __expf(p0);
        const float w1 = __expf(p1);
        esum0 += w0; esum1 += w1;
        const float2 w02 = make_float2(w0, w0);
        const float2 w12 = make_float2(w1, w1);
        acc2[0] = ffma2(w02, dA1, acc2[0]);
        acc2[1] = ffma2(w02, dA2, acc2[1]);
        acc2[2] = ffma2(w12, dB1, acc2[2]);
        acc2[3] = ffma2(w12, dB2, acc2[3]);
    }

    // ---- block reduction ----
    // j semantics: j = bi*4 + oj ; bi0=b_lo, bi1=b_hi ; oj -> o = 2tg+(oj&1)+8*(oj>>1)
    __shared__ float s_acc[WARPS][8][32];
    __shared__ float s_es[WARPS][16];
    s_acc[wid][0][lane] = acc2[0].x; s_acc[wid][1][lane] = acc2[0].y;
    s_acc[wid][2][lane] = acc2[1].x; s_acc[wid][3][lane] = acc2[1].y;
    s_acc[wid][4][lane] = acc2[2].x; s_acc[wid][5][lane] = acc2[2].y;
    s_acc[wid][6][lane] = acc2[3].x; s_acc[wid][7][lane] = acc2[3].y;
    if (tg == 0) {
        s_es[wid][g]     = esum0;
        s_es[wid][g + 8] = esum1;
    }
    __syncthreads();

#pragma unroll
    for (int pass = 0; pass < 2; pass++) {
        const int cell = pass * 256 + tid;      // 9 bits: pb(1) j(3) lane(5)
        const int cpb  = (cell >> 8) & 1;
        const int j    = (cell >> 5) & 7;
        const int ln   = cell & 31;
        float s = 0.f;
#pragma unroll
        for (int q = 0; q < PAIRS; q++) s += s_acc[2 * q + cpb][j][ln];
        const int b = (ln >> 2) + 8 * (j >> 2) + 16 * cpb;
        const int o = ((ln & 3) << 1) + (j & 1) + 8 * ((j >> 1) & 1);
        atomicAdd(&g_sraw[(b * Cn + c) * 16 + o], s);
    }
    if (tid < 32) {
        const int cpb = tid >> 4;
        float s = 0.f;
#pragma unroll
        for (int q = 0; q < PAIRS; q++) s += s_es[2 * q + cpb][tid & 15];
        atomicAdd(&g_sumexp[tid * Cn + c], s);
    }
}

// ---------------- K4: v1 = squash(s1), vsum = v0+v1, reset accumulators ----
__global__ void k_v1() {
    int t = blockIdx.x * blockDim.x + threadIdx.x;
    if (t >= Bsz * Cn) return;
    const float inv = 1.f / g_sumexp[t];
    float s[16], n2 = 0.f;
#pragma unroll
    for (int o = 0; o < 16; o++) { s[o] = g_sraw[t * 16 + o] * inv; n2 += s[o] * s[o]; }
    const float norm = sqrtf(n2);
    const float sc = norm / (1.f + n2);
#pragma unroll
    for (int o = 0; o < 16; o++) {
        g_vsum[t * 16 + o] = g_v0[t * 16 + o] + sc * s[o];
        g_sraw[t * 16 + o] = 0.f;
    }
    g_sumexp[t] = 0.f;
}

// ---------------- K5: out = squash(s2) --------------------------------------
__global__ void k_out(float* __restrict__ out) {
    int t = blockIdx.x * blockDim.x + threadIdx.x;
    if (t >= Bsz * Cn) return;
    const float inv = 1.f / g_sumexp[t];
    float s[16], n2 = 0.f;
#pragma unroll
    for (int o = 0; o < 16; o++) { s[o] = g_sraw[t * 16 + o] * inv; n2 += s[o] * s[o]; }
    const float norm = sqrtf(n2);
    const float sc = norm / (1.f + n2);
#pragma unroll
    for (int o = 0; o < 16; o++) out[t * 16 + o] = sc * s[o];
}

// ---------------- launch ----------------------------------------------------
extern "C" void kernel_launch(void* const* d_in, const int* in_sizes, int n_in,
                              void* d_out, int out_size) {
    const float* x = (const float*)d_in[0];
    const float* W = (const float*)d_in[1];
    if (n_in >= 2 && in_sizes[0] > in_sizes[1]) {  // safety: x is 8192, W is 67M
        x = (const float*)d_in[1];
        W = (const float*)d_in[0];
    }
    float* out = (float*)d_out;

    float* d_v0   = nullptr;
    float* d_vsum = nullptr;
    cudaGetSymbolAddress((void**)&d_v0,   g_v0);
    cudaGetSymbolAddress((void**)&d_vsum, g_vsum);

    k_zero<<<32, 256>>>();
    k_prep<<<dim3(Rn / PRBLK, Cn), 256>>>(W);
    k_v0<<<2, 256>>>(x);

    // iteration 1 (uses v0) — reversed traversal: consume prep's L2 tail first
    k_route_mma<<<dim3(Rn / RBLK, Cn), 256>>>(x, d_v0, 1);
    k_v1<<<2, 256>>>();

    // iteration 2 (uses v0+v1) — forward: consume pass 1's L2 tail first
    k_route_mma<<<dim3(Rn / RBLK, Cn), 256>>>(x, d_vsum, 0);
    k_out<<<2, 256>>>(out);
}

// round 9
// speedup vs baseline: 1.1730x; 1.1730x over previous
#include <cuda_runtime.h>
#include <cuda_fp16.h>
#include <cstdint>
#include <cstddef>

// Problem constants
#define Bsz  32
#define Rn   16384
#define Cn   16
#define Od   16

#define WARPS 8
#define PAIRS 4                   // warp pairs per block (route)
#define RPW   64                  // r per warp-pair in route
#define RBLK  (PAIRS * RPW)       // 256 r per block
#define PRPW  32                  // r per warp in prep
#define PRBLK (WARPS * PRPW)      // 256 r per prep block

// ---------------- scratch (device globals; no allocation allowed) ----------
// +32 pad: route prefetch reads one uint4 row past the end harmlessly.
__device__ uint4 g_Wh4[(size_t)Rn * Cn * 32 + 32];  // 134 MB fp16 W, frag-packed
__device__ float g_Wsum[Cn * 256];              // sum over r of W  [c][o][i]
__device__ float g_v0[Bsz * Cn * Od];
__device__ float g_vsum[Bsz * Cn * Od];         // v0 + v1
__device__ float g_sraw[Bsz * Cn * Od];         // un-normalized weighted sums
__device__ float g_sumexp[Bsz * Cn];            // sum of exp(logit) per (b,c)

// ---------------- helpers ---------------------------------------------------
__device__ __forceinline__ uint32_t packh2(float a, float b) {
    __half2 h = __floats2half2_rn(a, b);
    return *reinterpret_cast<uint32_t*>(&h);
}

union F2U { float2 f; unsigned long long u; };

__device__ __forceinline__ float2 ffma2(float2 a, float2 b, float2 c) {
    F2U A, B, C, D; A.f = a; B.f = b; C.f = c;
    asm("fma.rn.f32x2 %0, %1, %2, %3;" : "=l"(D.u) : "l"(A.u), "l"(B.u), "l"(C.u));
    return D.f;
}
__device__ __forceinline__ float2 fmul2(float2 a, float2 b) {
    F2U A, B, D; A.f = a; B.f = b;
    asm("mul.rn.f32x2 %0, %1, %2;" : "=l"(D.u) : "l"(A.u), "l"(B.u));
    return D.f;
}

// mma m16n8k16: dA = rows g (b-low), dB = rows g+8 (b-high), cols = 2 o's
__device__ __forceinline__ void mma16816(float2& dA, float2& dB, const uint32_t* a,
                                         uint32_t b0, uint32_t b1) {
    asm volatile(
        "mma.sync.aligned.m16n8k16.row.col.f32.f16.f16.f32 "
        "{%0,%1,%2,%3}, {%4,%5,%6,%7}, {%8,%9}, {%10,%11,%12,%13};\n"
        : "=f"(dA.x), "=f"(dA.y), "=f"(dB.x), "=f"(dB.y)
        : "r"(a[0]), "r"(a[1]), "r"(a[2]), "r"(a[3]),
          "r"(b0), "r"(b1),
          "f"(0.f), "f"(0.f), "f"(0.f), "f"(0.f));
}

// ---------------- K0: zero accumulators (per replay) -----------------------
__global__ void k_zero() {
    int i = blockIdx.x * blockDim.x + threadIdx.x;
    if (i < Cn * 256)       g_Wsum[i] = 0.f;
    if (i < Bsz * Cn * Od)  g_sraw[i] = 0.f;
    if (i < Bsz * Cn)       g_sumexp[i] = 0.f;
}

// ---------------- K1: prep — convert W to packed fp16 frags + Wsum ---------
__global__ __launch_bounds__(256) void k_prep(const float* __restrict__ W) {
    const int c    = blockIdx.y;
    const int tid  = threadIdx.x;
    const int wid  = tid >> 5;
    const int lane = tid & 31;
    const int g    = lane >> 2;
    const int tg   = lane & 3;
    const int r0   = blockIdx.x * PRBLK + wid * PRPW;

    float ws[8];
#pragma unroll
    for (int j = 0; j < 8; j++) ws[j] = 0.f;

#pragma unroll 8
    for (int k = 0; k < PRPW; k++) {
        const float2* row = reinterpret_cast<const float2*>(
            &W[((size_t)(r0 + k) * Cn + c) * 256]);
        float2 f0 = __ldcs(&row[g * 8 + tg]);
        float2 f1 = __ldcs(&row[g * 8 + tg + 4]);
        float2 f2 = __ldcs(&row[(g + 8) * 8 + tg]);
        float2 f3 = __ldcs(&row[(g + 8) * 8 + tg + 4]);
        ws[0] += f0.x; ws[1] += f0.y; ws[2] += f1.x; ws[3] += f1.y;
        ws[4] += f2.x; ws[5] += f2.y; ws[6] += f3.x; ws[7] += f3.y;
        uint4 o;
        o.x = packh2(f0.x, f0.y); o.y = packh2(f1.x, f1.y);
        o.z = packh2(f2.x, f2.y); o.w = packh2(f3.x, f3.y);
        // plain store (cache-all): keep the write tail resident in L2 for route-1
        g_Wh4[((size_t)c * Rn + (r0 + k)) * 32 + lane] = o;
    }

    // fold Wsum partials: positions per lane are a bijection onto 0..255
    __shared__ float s_ws[WARPS][256];
    const int p0 = g * 16 + 2 * tg;        // (o=g,   i=2tg)
    const int p2 = (g + 8) * 16 + 2 * tg;  // (o=g+8, i=2tg)
    s_ws[wid][p0]     = ws[0]; s_ws[wid][p0 + 1] = ws[1];
    s_ws[wid][p0 + 8] = ws[2]; s_ws[wid][p0 + 9] = ws[3];
    s_ws[wid][p2]     = ws[4]; s_ws[wid][p2 + 1] = ws[5];
    s_ws[wid][p2 + 8] = ws[6]; s_ws[wid][p2 + 9] = ws[7];
    __syncthreads();
    float s = 0.f;
#pragma unroll
    for (int w = 0; w < WARPS; w++) s += s_ws[w][tid];
    atomicAdd(&g_Wsum[c * 256 + tid], s);
}

// ---------------- K2: v0 = squash((1/R) * Wsum . x) ------------------------
__global__ void k_v0(const float* __restrict__ x) {
    int t = blockIdx.x * blockDim.x + threadIdx.x;
    if (t >= Bsz * Cn) return;
    const int b = t >> 4, c = t & 15;
    float s[16], n2 = 0.f;
#pragma unroll
    for (int o = 0; o < 16; o++) {
        float acc = 0.f;
#pragma unroll
        for (int i = 0; i < 16; i++)
            acc = fmaf(g_Wsum[(c * 16 + o) * 16 + i], x[(b * Cn + c) * 16 + i], acc);
        acc *= (1.f / (float)Rn);
        s[o] = acc; n2 += acc * acc;
    }
    const float norm = sqrtf(n2);
    const float sc = norm / (1.f + n2);
#pragma unroll
    for (int o = 0; o < 16; o++) g_v0[t * 16 + o] = sc * s[o];
}

// ---------------- K3: fused routing pass (HMMA, b split across warp pairs) --
// Identical inner structure to the verified 40.1us config (64 regs, 4 blk/SM,
// depth-1 prefetch). Only change: rev flips the r-chunk traversal order so
// consecutive passes meet each other's L2-resident tail (g_Wh4 = 134MB vs
// 126MB L2 — two-pass Belady pairing).
__global__ __launch_bounds__(256, 4) void k_route_mma(const float* __restrict__ x,
                                                      const float* __restrict__ vsrc,
                                                      int rev) {
    const int bx   = rev ? (gridDim.x - 1 - blockIdx.x) : blockIdx.x;
    const int c    = blockIdx.y;
    const int tid  = threadIdx.x;
    const int wid  = tid >> 5;
    const int lane = tid & 31;
    const int g    = lane >> 2;
    const int tg   = lane & 3;
    const int pair = wid >> 1;
    const int pb   = wid & 1;     // b-half: 0 -> b 0-15, 1 -> b 16-31

    // ---- A fragments from x (fp32 -> fp16), M = 16 b's of this half ----
    uint32_t A[4];
    {
        const int b_lo = pb * 16 + g, b_hi = pb * 16 + 8 + g;
#pragma unroll
        for (int kh = 0; kh < 2; kh++) {
            float2 lo = *reinterpret_cast<const float2*>(&x[(b_lo * Cn + c) * 16 + 2 * tg + kh * 8]);
            float2 hi = *reinterpret_cast<const float2*>(&x[(b_hi * Cn + c) * 16 + 2 * tg + kh * 8]);
            A[kh * 2 + 0] = packh2(lo.x, lo.y);
            A[kh * 2 + 1] = packh2(hi.x, hi.y);
        }
    }

    // ---- v pairs for this lane's (b,o) positions ----
    float2 vv2[4];
    {
        const int b_lo = pb * 16 + g, b_hi = pb * 16 + 8 + g;
        vv2[0] = *reinterpret_cast<const float2*>(&vsrc[(b_lo * Cn + c) * 16 + 2 * tg]);
        vv2[1] = *reinterpret_cast<const float2*>(&vsrc[(b_lo * Cn + c) * 16 + 2 * tg + 8]);
        vv2[2] = *reinterpret_cast<const float2*>(&vsrc[(b_hi * Cn + c) * 16 + 2 * tg]);
        vv2[3] = *reinterpret_cast<const float2*>(&vsrc[(b_hi * Cn + c) * 16 + 2 * tg + 8]);
    }

    float2 acc2[4];
#pragma unroll
    for (int j = 0; j < 4; j++) acc2[j] = make_float2(0.f, 0.f);
    float esum0 = 0.f, esum1 = 0.f;

    const int r0 = bx * RBLK + pair * RPW;
    const uint4* __restrict__ Wq = g_Wh4 + ((size_t)c * Rn + r0) * 32 + lane;

    uint4 nxt = *Wq;
#pragma unroll 4
    for (int k = 0; k < RPW; k++) {
        const uint4 cur = nxt;
        Wq += 32;
        nxt = *Wq;   // last iter reads 1 row past (padded) — harmless

        float2 dA1, dB1, dA2, dB2;
        mma16816(dA1, dB1, A, cur.x, cur.y);   // o 0-7   (dA=b_lo, dB=b_hi)
        mma16816(dA2, dB2, A, cur.z, cur.w);   // o 8-15

        // logit partials (each lane: its 4 o's), packed f32x2
        float2 q0 = ffma2(dA2, vv2[1], fmul2(dA1, vv2[0]));
        float2 q1 = ffma2(dB2, vv2[3], fmul2(dB1, vv2[2]));
        float p0 = q0.x + q0.y;
        float p1 = q1.x + q1.y;
        p0 += __shfl_xor_sync(0xffffffffu, p0, 1);
        p0 += __shfl_xor_sync(0xffffffffu, p0, 2);
        p1 += __shfl_xor_sync(0xffffffffu, p1, 1);
        p1 += __shfl_xor_sync(0xffffffffu, p1, 2);

        const float w0 = __expf(p0);
        const float w1 = __expf(p1);
        esum0 += w0; esum1 += w1;
        const float2 w02 = make_float2(w0, w0);
        const float2 w12 = make_float2(w1, w1);
        acc2[0] = ffma2(w02, dA1, acc2[0]);
        acc2[1] = ffma2(w02, dA2, acc2[1]);
        acc2[2] = ffma2(w12, dB1, acc2[2]);
        acc2[3] = ffma2(w12, dB2, acc2[3]);
    }

    // ---- block reduction ----
    // j semantics: j = bi*4 + oj ; bi0=b_lo, bi1=b_hi ; oj -> o = 2tg+(oj&1)+8*(oj>>1)
    __shared__ float s_acc[WARPS][8][32];
    __shared__ float s_es[WARPS][16];
    s_acc[wid][0][lane] = acc2[0].x; s_acc[wid][1][lane] = acc2[0].y;
    s_acc[wid][2][lane] = acc2[1].x; s_acc[wid][3][lane] = acc2[1].y;
    s_acc[wid][4][lane] = acc2[2].x; s_acc[wid][5][lane] = acc2[2].y;
    s_acc[wid][6][lane] = acc2[3].x; s_acc[wid][7][lane] = acc2[3].y;
    if (tg == 0) {
        s_es[wid][g]     = esum0;
        s_es[wid][g + 8] = esum1;
    }
    __syncthreads();

#pragma unroll
    for (int pass = 0; pass < 2; pass++) {
        const int cell = pass * 256 + tid;      // 9 bits: pb(1) j(3) lane(5)
        const int cpb  = (cell >> 8) & 1;
        const int j    = (cell >> 5) & 7;
        const int ln   = cell & 31;
        float s = 0.f;
#pragma unroll
        for (int q = 0; q < PAIRS; q++) s += s_acc[2 * q + cpb][j][ln];
        const int b = (ln >> 2) + 8 * (j >> 2) + 16 * cpb;
        const int o = ((ln & 3) << 1) + (j & 1) + 8 * ((j >> 1) & 1);
        atomicAdd(&g_sraw[(b * Cn + c) * 16 + o], s);
    }
    if (tid < 32) {
        const int cpb = tid >> 4;
        float s = 0.f;
#pragma unroll
        for (int q = 0; q < PAIRS; q++) s += s_es[2 * q + cpb][tid & 15];
        atomicAdd(&g_sumexp[tid * Cn + c], s);
    }
}

// ---------------- K4: v1 = squash(s1), vsum = v0+v1, reset accumulators ----
__global__ void k_v1() {
    int t = blockIdx.x * blockDim.x + threadIdx.x;
    if (t >= Bsz * Cn) return;
    const float inv = 1.f / g_sumexp[t];
    float s[16], n2 = 0.f;
#pragma unroll
    for (int o = 0; o < 16; o++) { s[o] = g_sraw[t * 16 + o] * inv; n2 += s[o] * s[o]; }
    const float norm = sqrtf(n2);
    const float sc = norm / (1.f + n2);
#pragma unroll
    for (int o = 0; o < 16; o++) {
        g_vsum[t * 16 + o] = g_v0[t * 16 + o] + sc * s[o];
        g_sraw[t * 16 + o] = 0.f;
    }
    g_sumexp[t] = 0.f;
}

// ---------------- K5: out = squash(s2) --------------------------------------
__global__ void k_out(float* __restrict__ out) {
    int t = blockIdx.x * blockDim.x + threadIdx.x;
    if (t >= Bsz * Cn) return;
    const float inv = 1.f / g_sumexp[t];
    float s[16], n2 = 0.f;
#pragma unroll
    for (int o = 0; o < 16; o++) { s[o] = g_sraw[t * 16 + o] * inv; n2 += s[o] * s[o]; }
    const float norm = sqrtf(n2);
    const float sc = norm / (1.f + n2);
#pragma unroll
    for (int o = 0; o < 16; o++) out[t * 16 + o] = sc * s[o];
}

// ---------------- launch ----------------------------------------------------
extern "C" void kernel_launch(void* const* d_in, const int* in_sizes, int n_in,
                              void* d_out, int out_size) {
    const float* x = (const float*)d_in[0];
    const float* W = (const float*)d_in[1];
    if (n_in >= 2 && in_sizes[0] > in_sizes[1]) {  // safety: x is 8192, W is 67M
        x = (const float*)d_in[1];
        W = (const float*)d_in[0];
    }
    float* out = (float*)d_out;

    float* d_v0   = nullptr;
    float* d_vsum = nullptr;
    cudaGetSymbolAddress((void**)&d_v0,   g_v0);
    cudaGetSymbolAddress((void**)&d_vsum, g_vsum);

    k_zero<<<32, 256>>>();
    k_prep<<<dim3(Rn / PRBLK, Cn), 256>>>(W);
    k_v0<<<2, 256>>>(x);

    // iteration 1 (uses v0) — reversed traversal: consume prep's L2 tail first
    k_route_mma<<<dim3(Rn / RBLK, Cn), 256>>>(x, d_v0, 1);
    k_v1<<<2, 256>>>();

    // iteration 2 (uses v0+v1) — forward: meet route-1's L2-resident low end
    k_route_mma<<<dim3(Rn / RBLK, Cn), 256>>>(x, d_vsum, 0);
    k_out<<<2, 256>>>(out);
}

// round 10
// speedup vs baseline: 1.2263x; 1.0455x over previous
#include <cuda_runtime.h>
#include <cuda_fp16.h>
#include <cstdint>
#include <cstddef>

// Problem constants
#define Bsz  32
#define Rn   16384
#define Cn   16
#define Od   16

#define WARPS 8
#define PAIRS 4                   // warp pairs per block (route)
#define RPW   64                  // r per warp-pair in route
#define RBLK  (PAIRS * RPW)       // 256 r per block
#define PRPW  32                  // r per warp in prep
#define PRBLK (WARPS * PRPW)      // 256 r per prep block

#define PRE   6                   // cp.async prefetch distance
#define SLOTS 8                   // smem ring slots per warp

// ---------------- scratch (device globals; no allocation allowed) ----------
__device__ uint4 g_Wh4[(size_t)Rn * Cn * 32 + 32];  // 134 MB fp16 W, frag-packed
__device__ float g_Wsum[Cn * 256];              // sum over r of W  [c][o][i]
__device__ float g_v0[Bsz * Cn * Od];
__device__ float g_vsum[Bsz * Cn * Od];         // v0 + v1
__device__ float g_sraw[Bsz * Cn * Od];         // un-normalized weighted sums
__device__ float g_sumexp[Bsz * Cn];            // sum of exp(logit) per (b,c)

// ---------------- helpers ---------------------------------------------------
__device__ __forceinline__ uint32_t packh2(float a, float b) {
    __half2 h = __floats2half2_rn(a, b);
    return *reinterpret_cast<uint32_t*>(&h);
}

union F2U { float2 f; unsigned long long u; };

__device__ __forceinline__ float2 ffma2(float2 a, float2 b, float2 c) {
    F2U A, B, C, D; A.f = a; B.f = b; C.f = c;
    asm("fma.rn.f32x2 %0, %1, %2, %3;" : "=l"(D.u) : "l"(A.u), "l"(B.u), "l"(C.u));
    return D.f;
}
__device__ __forceinline__ float2 fmul2(float2 a, float2 b) {
    F2U A, B, D; A.f = a; B.f = b;
    asm("mul.rn.f32x2 %0, %1, %2;" : "=l"(D.u) : "l"(A.u), "l"(B.u));
    return D.f;
}

__device__ __forceinline__ uint32_t smem_u32(const void* p) {
    return (uint32_t)__cvta_generic_to_shared(p);
}
__device__ __forceinline__ void cp_async16(uint32_t saddr, const void* gptr) {
    asm volatile("cp.async.cg.shared.global [%0], [%1], 16;\n"
                 :: "r"(saddr), "l"(gptr));
}
__device__ __forceinline__ void cp_commit() {
    asm volatile("cp.async.commit_group;\n");
}
template <int N>
__device__ __forceinline__ void cp_wait() {
    asm volatile("cp.async.wait_group %0;\n" :: "n"(N));
}

// mma m16n8k16: dA = rows g (b-low), dB = rows g+8 (b-high), cols = 2 o's
__device__ __forceinline__ void mma16816(float2& dA, float2& dB, const uint32_t* a,
                                         uint32_t b0, uint32_t b1) {
    asm volatile(
        "mma.sync.aligned.m16n8k16.row.col.f32.f16.f16.f32 "
        "{%0,%1,%2,%3}, {%4,%5,%6,%7}, {%8,%9}, {%10,%11,%12,%13};\n"
        : "=f"(dA.x), "=f"(dA.y), "=f"(dB.x), "=f"(dB.y)
        : "r"(a[0]), "r"(a[1]), "r"(a[2]), "r"(a[3]),
          "r"(b0), "r"(b1),
          "f"(0.f), "f"(0.f), "f"(0.f), "f"(0.f));
}

// ---------------- K0: zero accumulators (per replay) -----------------------
__global__ void k_zero() {
    int i = blockIdx.x * blockDim.x + threadIdx.x;
    if (i < Cn * 256)       g_Wsum[i] = 0.f;
    if (i < Bsz * Cn * Od)  g_sraw[i] = 0.f;
    if (i < Bsz * Cn)       g_sumexp[i] = 0.f;
}

// ---------------- K1: prep — convert W to packed fp16 frags + Wsum ---------
__global__ __launch_bounds__(256) void k_prep(const float* __restrict__ W) {
    const int c    = blockIdx.y;
    const int tid  = threadIdx.x;
    const int wid  = tid >> 5;
    const int lane = tid & 31;
    const int g    = lane >> 2;
    const int tg   = lane & 3;
    const int r0   = blockIdx.x * PRBLK + wid * PRPW;

    float ws[8];
#pragma unroll
    for (int j = 0; j < 8; j++) ws[j] = 0.f;

#pragma unroll 8
    for (int k = 0; k < PRPW; k++) {
        const float2* row = reinterpret_cast<const float2*>(
            &W[((size_t)(r0 + k) * Cn + c) * 256]);
        float2 f0 = __ldcs(&row[g * 8 + tg]);
        float2 f1 = __ldcs(&row[g * 8 + tg + 4]);
        float2 f2 = __ldcs(&row[(g + 8) * 8 + tg]);
        float2 f3 = __ldcs(&row[(g + 8) * 8 + tg + 4]);
        ws[0] += f0.x; ws[1] += f0.y; ws[2] += f1.x; ws[3] += f1.y;
        ws[4] += f2.x; ws[5] += f2.y; ws[6] += f3.x; ws[7] += f3.y;
        uint4 o;
        o.x = packh2(f0.x, f0.y); o.y = packh2(f1.x, f1.y);
        o.z = packh2(f2.x, f2.y); o.w = packh2(f3.x, f3.y);
        g_Wh4[((size_t)c * Rn + (r0 + k)) * 32 + lane] = o;
    }

    // fold Wsum partials: positions per lane are a bijection onto 0..255
    __shared__ float s_ws[WARPS][256];
    const int p0 = g * 16 + 2 * tg;        // (o=g,   i=2tg)
    const int p2 = (g + 8) * 16 + 2 * tg;  // (o=g+8, i=2tg)
    s_ws[wid][p0]     = ws[0]; s_ws[wid][p0 + 1] = ws[1];
    s_ws[wid][p0 + 8] = ws[2]; s_ws[wid][p0 + 9] = ws[3];
    s_ws[wid][p2]     = ws[4]; s_ws[wid][p2 + 1] = ws[5];
    s_ws[wid][p2 + 8] = ws[6]; s_ws[wid][p2 + 9] = ws[7];
    __syncthreads();
    float s = 0.f;
#pragma unroll
    for (int w = 0; w < WARPS; w++) s += s_ws[w][tid];
    atomicAdd(&g_Wsum[c * 256 + tid], s);
}

// ---------------- K2: v0 = squash((1/R) * Wsum . x) ------------------------
__global__ void k_v0(const float* __restrict__ x) {
    int t = blockIdx.x * blockDim.x + threadIdx.x;
    if (t >= Bsz * Cn) return;
    const int b = t >> 4, c = t & 15;
    float s[16], n2 = 0.f;
#pragma unroll
    for (int o = 0; o < 16; o++) {
        float acc = 0.f;
#pragma unroll
        for (int i = 0; i < 16; i++)
            acc = fmaf(g_Wsum[(c * 16 + o) * 16 + i], x[(b * Cn + c) * 16 + i], acc);
        acc *= (1.f / (float)Rn);
        s[o] = acc; n2 += acc * acc;
    }
    const float norm = sqrtf(n2);
    const float sc = norm / (1.f + n2);
#pragma unroll
    for (int o = 0; o < 16; o++) g_v0[t * 16 + o] = sc * s[o];
}

// ---------------- K3: fused routing pass (HMMA + cp.async pipeline) ---------
// Per-warp depth-PRE cp.async pipeline feeding a smem ring (SLOTS x 512B).
// Per r: wait_group -> LDS.128 -> 2x mma.m16n8k16 -> f32x2 logit dot ->
// 4 SHFL -> 2 exp -> f32x2 accumulate. Registers hold no in-flight W data.
__global__ __launch_bounds__(256, 4) void k_route_mma(const float* __restrict__ x,
                                                      const float* __restrict__ vsrc,
                                                      int rev) {
    __shared__ __align__(16) uint4 s_w[WARPS][SLOTS][32];

    const int bx   = rev ? (gridDim.x - 1 - blockIdx.x) : blockIdx.x;
    const int c    = blockIdx.y;
    const int tid  = threadIdx.x;
    const int wid  = tid >> 5;
    const int lane = tid & 31;
    const int g    = lane >> 2;
    const int tg   = lane & 3;
    const int pair = wid >> 1;
    const int pb   = wid & 1;     // b-half: 0 -> b 0-15, 1 -> b 16-31

    // ---- A fragments from x (fp32 -> fp16), M = 16 b's of this half ----
    uint32_t A[4];
    {
        const int b_lo = pb * 16 + g, b_hi = pb * 16 + 8 + g;
#pragma unroll
        for (int kh = 0; kh < 2; kh++) {
            float2 lo = *reinterpret_cast<const float2*>(&x[(b_lo * Cn + c) * 16 + 2 * tg + kh * 8]);
            float2 hi = *reinterpret_cast<const float2*>(&x[(b_hi * Cn + c) * 16 + 2 * tg + kh * 8]);
            A[kh * 2 + 0] = packh2(lo.x, lo.y);
            A[kh * 2 + 1] = packh2(hi.x, hi.y);
        }
    }

    // ---- v pairs for this lane's (b,o) positions ----
    float2 vv2[4];
    {
        const int b_lo = pb * 16 + g, b_hi = pb * 16 + 8 + g;
        vv2[0] = *reinterpret_cast<const float2*>(&vsrc[(b_lo * Cn + c) * 16 + 2 * tg]);
        vv2[1] = *reinterpret_cast<const float2*>(&vsrc[(b_lo * Cn + c) * 16 + 2 * tg + 8]);
        vv2[2] = *reinterpret_cast<const float2*>(&vsrc[(b_hi * Cn + c) * 16 + 2 * tg]);
        vv2[3] = *reinterpret_cast<const float2*>(&vsrc[(b_hi * Cn + c) * 16 + 2 * tg + 8]);
    }

    float2 acc2[4];
#pragma unroll
    for (int j = 0; j < 4; j++) acc2[j] = make_float2(0.f, 0.f);
    float esum0 = 0.f, esum1 = 0.f;

    const int r0 = bx * RBLK + pair * RPW;
    const uint4* __restrict__ gsrc = g_Wh4 + ((size_t)c * Rn + r0) * 32 + lane;
    const uint32_t sbase = smem_u32(&s_w[wid][0][lane]);

    // ---- pipeline prologue: issue PRE copies (one group each) ----
#pragma unroll
    for (int j = 0; j < PRE; j++) {
        cp_async16(sbase + j * 512, gsrc + (size_t)j * 32);
        cp_commit();
    }

#pragma unroll 8
    for (int k = 0; k < RPW; k++) {
        cp_wait<PRE - 1>();                       // slot k ready
        const uint4 cur = s_w[wid][k & (SLOTS - 1)][lane];
        if (k + PRE < RPW)
            cp_async16(sbase + ((k + PRE) & (SLOTS - 1)) * 512,
                       gsrc + (size_t)(k + PRE) * 32);
        cp_commit();                              // one group per iteration

        float2 dA1, dB1, dA2, dB2;
        mma16816(dA1, dB1, A, cur.x, cur.y);   // o 0-7   (dA=b_lo, dB=b_hi)
        mma16816(dA2, dB2, A, cur.z, cur.w);   // o 8-15

        // logit partials (each lane: its 4 o's), packed f32x2
        float2 q0 = ffma2(dA2, vv2[1], fmul2(dA1, vv2[0]));
        float2 q1 = ffma2(dB2, vv2[3], fmul2(dB1, vv2[2]));
        float p0 = q0.x + q0.y;
        float p1 = q1.x + q1.y;
        p0 += __shfl_xor_sync(0xffffffffu, p0, 1);
        p0 += __shfl_xor_sync(0xffffffffu, p0, 2);
        p1 += __shfl_xor_sync(0xffffffffu, p1, 1);
        p1 += __shfl_xor_sync(0xffffffffu, p1, 2);

        const float w0 = __expf(p0);
        const float w1 = __expf(p1);
        esum0 += w0; esum1 += w1;
        const float2 w02 = make_float2(w0, w0);
        const float2 w12 = make_float2(w1, w1);
        acc2[0] = ffma2(w02, dA1, acc2[0]);
        acc2[1] = ffma2(w02, dA2, acc2[1]);
        acc2[2] = ffma2(w12, dB1, acc2[2]);
        acc2[3] = ffma2(w12, dB2, acc2[3]);
    }

    // ---- block reduction ----
    // j semantics: j = bi*4 + oj ; bi0=b_lo, bi1=b_hi ; oj -> o = 2tg+(oj&1)+8*(oj>>1)
    __shared__ float s_acc[WARPS][8][32];
    __shared__ float s_es[WARPS][16];
    s_acc[wid][0][lane] = acc2[0].x; s_acc[wid][1][lane] = acc2[0].y;
    s_acc[wid][2][lane] = acc2[1].x; s_acc[wid][3][lane] = acc2[1].y;
    s_acc[wid][4][lane] = acc2[2].x; s_acc[wid][5][lane] = acc2[2].y;
    s_acc[wid][6][lane] = acc2[3].x; s_acc[wid][7][lane] = acc2[3].y;
    if (tg == 0) {
        s_es[wid][g]     = esum0;
        s_es[wid][g + 8] = esum1;
    }
    __syncthreads();

#pragma unroll
    for (int pass = 0; pass < 2; pass++) {
        const int cell = pass * 256 + tid;      // 9 bits: pb(1) j(3) lane(5)
        const int cpb  = (cell >> 8) & 1;
        const int j    = (cell >> 5) & 7;
        const int ln   = cell & 31;
        float s = 0.f;
#pragma unroll
        for (int q = 0; q < PAIRS; q++) s += s_acc[2 * q + cpb][j][ln];
        const int b = (ln >> 2) + 8 * (j >> 2) + 16 * cpb;
        const int o = ((ln & 3) << 1) + (j & 1) + 8 * ((j >> 1) & 1);
        atomicAdd(&g_sraw[(b * Cn + c) * 16 + o], s);
    }
    if (tid < 32) {
        const int cpb = tid >> 4;
        float s = 0.f;
#pragma unroll
        for (int q = 0; q < PAIRS; q++) s += s_es[2 * q + cpb][tid & 15];
        atomicAdd(&g_sumexp[tid * Cn + c], s);
    }
}

// ---------------- K4: v1 = squash(s1), vsum = v0+v1, reset accumulators ----
__global__ void k_v1() {
    int t = blockIdx.x * blockDim.x + threadIdx.x;
    if (t >= Bsz * Cn) return;
    const float inv = 1.f / g_sumexp[t];
    float s[16], n2 = 0.f;
#pragma unroll
    for (int o = 0; o < 16; o++) { s[o] = g_sraw[t * 16 + o] * inv; n2 += s[o] * s[o]; }
    const float norm = sqrtf(n2);
    const float sc = norm / (1.f + n2);
#pragma unroll
    for (int o = 0; o < 16; o++) {
        g_vsum[t * 16 + o] = g_v0[t * 16 + o] + sc * s[o];
        g_sraw[t * 16 + o] = 0.f;
    }
    g_sumexp[t] = 0.f;
}

// ---------------- K5: out = squash(s2) --------------------------------------
__global__ void k_out(float* __restrict__ out) {
    int t = blockIdx.x * blockDim.x + threadIdx.x;
    if (t >= Bsz * Cn) return;
    const float inv = 1.f / g_sumexp[t];
    float s[16], n2 = 0.f;
#pragma unroll
    for (int o = 0; o < 16; o++) { s[o] = g_sraw[t * 16 + o] * inv; n2 += s[o] * s[o]; }
    const float norm = sqrtf(n2);
    const float sc = norm / (1.f + n2);
#pragma unroll
    for (int o = 0; o < 16; o++) out[t * 16 + o] = sc * s[o];
}

// ---------------- launch ----------------------------------------------------
extern "C" void kernel_launch(void* const* d_in, const int* in_sizes, int n_in,
                              void* d_out, int out_size) {
    const float* x = (const float*)d_in[0];
    const float* W = (const float*)d_in[1];
    if (n_in >= 2 && in_sizes[0] > in_sizes[1]) {  // safety: x is 8192, W is 67M
        x = (const float*)d_in[1];
        W = (const float*)d_in[0];
    }
    float* out = (float*)d_out;

    float* d_v0   = nullptr;
    float* d_vsum = nullptr;
    cudaGetSymbolAddress((void**)&d_v0,   g_v0);
    cudaGetSymbolAddress((void**)&d_vsum, g_vsum);

    k_zero<<<32, 256>>>();
    k_prep<<<dim3(Rn / PRBLK, Cn), 256>>>(W);
    k_v0<<<2, 256>>>(x);

    // iteration 1 (uses v0)
    k_route_mma<<<dim3(Rn / RBLK, Cn), 256>>>(x, d_v0, 1);
    k_v1<<<2, 256>>>();

    // iteration 2 (uses v0+v1)
    k_route_mma<<<dim3(Rn / RBLK, Cn), 256>>>(x, d_vsum, 0);
    k_out<<<2, 256>>>(out);
}